// round 7
// baseline (speedup 1.0000x reference)
#include <cuda_runtime.h>
#include <cuda_fp16.h>
#include <math.h>
#include <stdint.h>

#define NN 4096
#define HH 64
#define KSPLIT 9
#define LSCALE 256.0f
#define LDESCALE (1.0f / 256.0f)

// ---------------------------------------------------------------- scratch
__device__ float d_wiu[NN * HH];
__device__ float d_h[NN * HH];
__device__ float d_part[KSPLIT * NN * HH];
__device__ __half d_Lhi[(size_t)NN * NN];     // 256*L hi
__device__ __half d_Llo[(size_t)NN * NN];     // 256*L lo
__device__ __half d_gAhi[HH * NN];            // g^T ping-pong buffers
__device__ __half d_gAlo[HH * NN];
__device__ __half d_gBhi[HH * NN];
__device__ __half d_gBlo[HH * NN];
__device__ unsigned int d_cnt[32];            // split-K tickets (mod KSPLIT)

// ---------------------------------------------------------------- PTX utils
__device__ __forceinline__ uint32_t smem_u32(const void* p) {
    uint32_t a;
    asm("{ .reg .u64 t; cvta.to.shared.u64 t, %1; cvt.u32.u64 %0, t; }"
        : "=r"(a) : "l"(p));
    return a;
}
#define SWZ128(o) ((o) ^ (((o) >> 3) & 0x70))

__device__ __forceinline__ void cp16(uint32_t s, const void* g) {
    asm volatile("cp.async.cg.shared.global [%0], [%1], 16;" :: "r"(s), "l"(g));
}
#define CP_COMMIT() asm volatile("cp.async.commit_group;" ::: "memory")
#define CP_WAIT1()  asm volatile("cp.async.wait_group 1;" ::: "memory")

__device__ __forceinline__ void ldsm_x4(uint32_t* r, uint32_t addr) {
    asm volatile("ldmatrix.sync.aligned.m8n8.x4.shared.b16 {%0,%1,%2,%3}, [%4];"
        : "=r"(r[0]), "=r"(r[1]), "=r"(r[2]), "=r"(r[3]) : "r"(addr));
}

__device__ __forceinline__ void mma16816(float* c, const uint32_t* a,
                                         uint32_t b0, uint32_t b1) {
    asm volatile(
        "mma.sync.aligned.m16n8k16.row.col.f32.f16.f16.f32 "
        "{%0,%1,%2,%3}, {%4,%5,%6,%7}, {%8,%9}, {%0,%1,%2,%3};"
        : "+f"(c[0]), "+f"(c[1]), "+f"(c[2]), "+f"(c[3])
        : "r"(a[0]), "r"(a[1]), "r"(a[2]), "r"(a[3]), "r"(b0), "r"(b1));
}

// ---------------------------------------------------------------- L split (once)
__global__ __launch_bounds__(256, 4) void lsplit_k(
    const float* __restrict__ L,
    __half* __restrict__ Lhi, __half* __restrict__ Llo)
{
    size_t i = ((size_t)blockIdx.x * 256 + threadIdx.x) * 4;
    float4 v = *(const float4*)(L + i);
    float s0 = v.x * LSCALE, s1 = v.y * LSCALE, s2 = v.z * LSCALE, s3 = v.w * LSCALE;
    __half h0 = __float2half_rn(s0), h1 = __float2half_rn(s1);
    __half h2 = __float2half_rn(s2), h3 = __float2half_rn(s3);
    __half l0 = __float2half_rn(s0 - __half2float(h0));
    __half l1 = __float2half_rn(s1 - __half2float(h1));
    __half l2 = __float2half_rn(s2 - __half2float(h2));
    __half l3 = __float2half_rn(s3 - __half2float(h3));
    __half2 hp0 = __halves2half2(h0, h1), hp1 = __halves2half2(h2, h3);
    __half2 lp0 = __halves2half2(l0, l1), lp1 = __halves2half2(l2, l3);
    *(uint2*)(Lhi + i) = make_uint2(*(uint32_t*)&hp0, *(uint32_t*)&hp1);
    *(uint2*)(Llo + i) = make_uint2(*(uint32_t*)&lp0, *(uint32_t*)&lp1);
}

// ---------------------------------------------------------------- wiu small GEMM
__global__ __launch_bounds__(256, 1) void small_gemm_k(
    const float* __restrict__ A, const float* __restrict__ W,
    float* __restrict__ out)
{
    __shared__ float As[64][65];
    __shared__ float Ws[64][68];
    const int tid = threadIdx.x;
    const int base = blockIdx.x * (64 * 64);
    for (int i = tid; i < 4096; i += 256) {
        Ws[i & 63][i >> 6] = W[i];
        As[i >> 6][i & 63] = A[base + i];
    }
    __syncthreads();
    const int r = tid & 63, cg = tid >> 6;
    float acc[16];
#pragma unroll
    for (int j = 0; j < 16; ++j) acc[j] = 0.f;
#pragma unroll 8
    for (int k = 0; k < 64; ++k) {
        float a = As[r][k];
        const float* wr = &Ws[k][cg << 4];
        float4 b0 = *(const float4*)(wr + 0);
        float4 b1 = *(const float4*)(wr + 4);
        float4 b2 = *(const float4*)(wr + 8);
        float4 b3 = *(const float4*)(wr + 12);
        acc[0]  = fmaf(a, b0.x, acc[0]);  acc[1]  = fmaf(a, b0.y, acc[1]);
        acc[2]  = fmaf(a, b0.z, acc[2]);  acc[3]  = fmaf(a, b0.w, acc[3]);
        acc[4]  = fmaf(a, b1.x, acc[4]);  acc[5]  = fmaf(a, b1.y, acc[5]);
        acc[6]  = fmaf(a, b1.z, acc[6]);  acc[7]  = fmaf(a, b1.w, acc[7]);
        acc[8]  = fmaf(a, b2.x, acc[8]);  acc[9]  = fmaf(a, b2.y, acc[9]);
        acc[10] = fmaf(a, b2.z, acc[10]); acc[11] = fmaf(a, b2.w, acc[11]);
        acc[12] = fmaf(a, b3.x, acc[12]); acc[13] = fmaf(a, b3.y, acc[13]);
        acc[14] = fmaf(a, b3.z, acc[14]); acc[15] = fmaf(a, b3.w, acc[15]);
    }
    float* op = out + base + r * 64 + (cg << 4);
    *(float4*)(op + 0)  = make_float4(acc[0],  acc[1],  acc[2],  acc[3]);
    *(float4*)(op + 4)  = make_float4(acc[4],  acc[5],  acc[6],  acc[7]);
    *(float4*)(op + 8)  = make_float4(acc[8],  acc[9],  acc[10], acc[11]);
    *(float4*)(op + 12) = make_float4(acc[12], acc[13], acc[14], acc[15]);
}

// ---------------------------------------------------------------- init: h=tanh(wiu), g split
__global__ __launch_bounds__(256, 2) void init_k(
    const float* __restrict__ wiu, const float* __restrict__ W,
    __half* __restrict__ gThi, __half* __restrict__ gTlo)
{
    __shared__ float Hs[32][65];
    __shared__ float Ws[64][68];
    const int tid = threadIdx.x;
    const int m0 = blockIdx.x * 32;

    for (int i = tid; i < 4096; i += 256)
        Ws[i & 63][i >> 6] = W[i];

    const int row = tid >> 3;
    const int c8 = (tid & 7) << 3;
    const int m = m0 + row;
    {
        const float* wp = wiu + m * 64 + c8;
        float4 a = *(const float4*)(wp), b = *(const float4*)(wp + 4);
        Hs[row][c8+0] = tanhf(a.x); Hs[row][c8+1] = tanhf(a.y);
        Hs[row][c8+2] = tanhf(a.z); Hs[row][c8+3] = tanhf(a.w);
        Hs[row][c8+4] = tanhf(b.x); Hs[row][c8+5] = tanhf(b.y);
        Hs[row][c8+6] = tanhf(b.z); Hs[row][c8+7] = tanhf(b.w);
    }
    __syncthreads();

    const int r2 = tid & 31;
    const int cg2 = tid >> 5;
    float ga[8];
#pragma unroll
    for (int j = 0; j < 8; ++j) ga[j] = 0.f;
#pragma unroll 8
    for (int k = 0; k < 64; ++k) {
        float a = Hs[r2][k];
        const float* wr = &Ws[k][cg2 << 3];
        float4 w0 = *(const float4*)(wr + 0);
        float4 w1 = *(const float4*)(wr + 4);
        ga[0] = fmaf(a, w0.x, ga[0]); ga[1] = fmaf(a, w0.y, ga[1]);
        ga[2] = fmaf(a, w0.z, ga[2]); ga[3] = fmaf(a, w0.w, ga[3]);
        ga[4] = fmaf(a, w1.x, ga[4]); ga[5] = fmaf(a, w1.y, ga[5]);
        ga[6] = fmaf(a, w1.z, ga[6]); ga[7] = fmaf(a, w1.w, ga[7]);
    }
#pragma unroll
    for (int j = 0; j < 8; ++j) {
        float v = ga[j];
        __half hi = __float2half_rn(v);
        __half lo = __float2half_rn(v - __half2float(hi));
        int col = (cg2 << 3) + j;
        gThi[col * NN + m0 + r2] = hi;
        gTlo[col * NN + m0 + r2] = lo;
    }
}

// ---------------------------------------------------------------- fused big HMMA GEMM + split-K reduce
// grid 288 = 32 M-tiles x 9 K-splits; block 256 (8 warps: 2m x 4n, warp m64n16)
// 2 stages x 48KB; last-arriving CTA per mtile reduces partials -> tanh -> g split
#define STAGE_BYTES 49152
#define NSTAGE 2

__device__ __forceinline__ void load_stage(
    uint32_t st, int kbase, int m0, int tid,
    const __half* __restrict__ Lhi, const __half* __restrict__ Llo,
    const __half* __restrict__ gThi, const __half* __restrict__ gTlo)
{
#pragma unroll
    for (int r = 0; r < 4; ++r) {
        int o = tid + 256 * r;
        int row = o >> 3, seg = o & 7;
        uint32_t soff = SWZ128((uint32_t)(row * 128 + seg * 16));
        size_t goff = (size_t)(m0 + row) * NN + kbase + seg * 8;
        cp16(st + soff,         Lhi + goff);
        cp16(st + 16384 + soff, Llo + goff);
    }
#pragma unroll
    for (int r = 0; r < 2; ++r) {
        int o = tid + 256 * r;
        int row = o >> 3, seg = o & 7;
        uint32_t soff = SWZ128((uint32_t)(row * 128 + seg * 16));
        size_t goff = (size_t)row * NN + kbase + seg * 8;
        cp16(st + 32768 + soff, gThi + goff);
        cp16(st + 40960 + soff, gTlo + goff);
    }
    CP_COMMIT();
}

__global__ __launch_bounds__(256, 2) void bigmma_k(
    const __half* __restrict__ Lhi, const __half* __restrict__ Llo,
    const __half* __restrict__ ginhi, const __half* __restrict__ ginlo,
    float* __restrict__ part, const float* __restrict__ wiu,
    const float* __restrict__ W, float* __restrict__ h,
    __half* __restrict__ gouthi, __half* __restrict__ goutlo,
    float* __restrict__ outf, int col_off, int last)
{
    extern __shared__ __align__(1024) char smem[];
    const uint32_t sb = smem_u32(smem);
    const int tid = threadIdx.x;
    const int wid = tid >> 5, lane = tid & 31;
    const int mtile = blockIdx.x / KSPLIT, ks = blockIdx.x % KSPLIT;
    const int m0 = mtile * 128;
    const int cstart = ks * 7;                 // chunk start (64-k units)
    const int nchunk = (ks == 8) ? 8 : 7;      // 8*7 + 8 = 64 chunks total
    const int kbase0 = cstart * 64;

    const int wm = wid >> 2;
    const int wn = wid & 3;
    const int lrow8 = (lane & 7) + ((lane >> 3) & 1) * 8;
    const int lk16  = (lane >> 4) * 16;

    uint32_t arow[4];
#pragma unroll
    for (int t = 0; t < 4; ++t)
        arow[t] = (uint32_t)(wm * 64 + t * 16 + lrow8) * 128;
    const uint32_t brow = (uint32_t)(wn * 16 + lrow8) * 128;

    float acc[4][2][4];
#pragma unroll
    for (int t = 0; t < 4; ++t)
#pragma unroll
        for (int g = 0; g < 2; ++g)
#pragma unroll
            for (int j = 0; j < 4; ++j) acc[t][g][j] = 0.f;

#pragma unroll
    for (int c = 0; c < NSTAGE; ++c)
        load_stage(sb + c * STAGE_BYTES, kbase0 + c * 64, m0, tid,
                   Lhi, Llo, ginhi, ginlo);

#pragma unroll 1
    for (int c = 0; c < nchunk; ++c) {
        CP_WAIT1();
        __syncthreads();

        const uint32_t st = sb + (c & 1) * STAGE_BYTES;
        const uint32_t stAhi = st, stAlo = st + 16384;
        const uint32_t stBhi = st + 32768, stBlo = st + 40960;

#pragma unroll
        for (int j = 0; j < 4; ++j) {
            const uint32_t kb = (uint32_t)(j * 32) + lk16;

            uint32_t bh[4], bl[4];
            ldsm_x4(bh, stBhi + SWZ128(brow + kb));
            ldsm_x4(bl, stBlo + SWZ128(brow + kb));

            uint32_t ah[4][4], al[4][4];
#pragma unroll
            for (int t = 0; t < 4; ++t) {
                ldsm_x4(ah[t], stAhi + SWZ128(arow[t] + kb));
                ldsm_x4(al[t], stAlo + SWZ128(arow[t] + kb));
            }

#pragma unroll
            for (int t = 0; t < 4; ++t) {
                mma16816(acc[t][0], ah[t], bh[0], bh[2]);
                mma16816(acc[t][1], ah[t], bh[1], bh[3]);
                mma16816(acc[t][0], al[t], bh[0], bh[2]);
                mma16816(acc[t][1], al[t], bh[1], bh[3]);
                mma16816(acc[t][0], ah[t], bl[0], bl[2]);
                mma16816(acc[t][1], ah[t], bl[1], bl[3]);
            }
        }
        __syncthreads();

        if (c + NSTAGE < nchunk)
            load_stage(st, kbase0 + (c + NSTAGE) * 64, m0, tid,
                       Lhi, Llo, ginhi, ginlo);
        else
            CP_COMMIT();
    }

    // write partial tile
    {
        const int l4 = lane >> 2;
        const int l2 = (lane & 3) * 2;
        float* pbase = part + (size_t)ks * (NN * 64);
#pragma unroll
        for (int t = 0; t < 4; ++t) {
            int mrow = m0 + wm * 64 + t * 16 + l4;
            float* p0 = pbase + (size_t)mrow * 64 + wn * 16;
            float* p1 = p0 + 8 * 64;
            *(float2*)(p0 + l2)     = make_float2(acc[t][0][0], acc[t][0][1]);
            *(float2*)(p0 + 8 + l2) = make_float2(acc[t][1][0], acc[t][1][1]);
            *(float2*)(p1 + l2)     = make_float2(acc[t][0][2], acc[t][0][3]);
            *(float2*)(p1 + 8 + l2) = make_float2(acc[t][1][2], acc[t][1][3]);
        }
    }

    // ---- split-K ticket: last CTA per mtile reduces ----
    __shared__ unsigned s_red;
    __threadfence();
    __syncthreads();
    if (tid == 0) {
        unsigned old = atomicAdd(&d_cnt[mtile], 1u);
        s_red = ((old % KSPLIT) == KSPLIT - 1) ? 1u : 0u;
    }
    __syncthreads();
    if (!s_red) return;
    __threadfence();

    // reuse pipeline smem for reduction scratch
    float (*Hs)[65] = (float(*)[65])smem;                  // 128 x 65 = 33280 B
    float (*Ws)[68] = (float(*)[68])(smem + 33280);        // 64 x 68  = 17408 B

    if (!last) {
        for (int i = tid; i < 4096; i += 256)
            Ws[i & 63][i >> 6] = W[i];
    }

    // phase A: z = wiu + descale * sum(partials); h = tanh(z)
    {
        const int row = tid >> 1;
        const int c32 = (tid & 1) * 32;
        const int m = m0 + row;
        const float* wp = wiu + (size_t)m * 64 + c32;
#pragma unroll
        for (int q = 0; q < 8; ++q) {
            float4 a = *(const float4*)(wp + q * 4);
            float4 s = make_float4(0.f, 0.f, 0.f, 0.f);
#pragma unroll
            for (int p = 0; p < KSPLIT; ++p) {
                const float4 c = *(const float4*)(part + (size_t)p * (NN * 64)
                                                  + (size_t)m * 64 + c32 + q * 4);
                s.x += c.x; s.y += c.y; s.z += c.z; s.w += c.w;
            }
            float z0 = tanhf(a.x + s.x * LDESCALE);
            float z1 = tanhf(a.y + s.y * LDESCALE);
            float z2 = tanhf(a.z + s.z * LDESCALE);
            float z3 = tanhf(a.w + s.w * LDESCALE);
            if (last) {
                *(float4*)(h + (size_t)m * 64 + c32 + q * 4) = make_float4(z0, z1, z2, z3);
                *(float4*)(outf + (size_t)m * 128 + col_off + c32 + q * 4) =
                    make_float4(z0, z1, z2, z3);
            } else {
                Hs[row][c32 + q * 4 + 0] = z0;
                Hs[row][c32 + q * 4 + 1] = z1;
                Hs[row][c32 + q * 4 + 2] = z2;
                Hs[row][c32 + q * 4 + 3] = z3;
            }
        }
    }
    if (last) return;
    __syncthreads();

    // phase B: g = h @ W^T for 128 rows; thread = (4 rows strided 32) x (8 cols)
    {
        const int rg = tid & 31;         // rows rg, rg+32, rg+64, rg+96
        const int cg = tid >> 5;         // cols cg*8 .. +8
        float ga[4][8];
#pragma unroll
        for (int i = 0; i < 4; ++i)
#pragma unroll
            for (int j = 0; j < 8; ++j) ga[i][j] = 0.f;

#pragma unroll 4
        for (int k = 0; k < 64; ++k) {
            float a0 = Hs[rg +  0][k];
            float a1 = Hs[rg + 32][k];
            float a2 = Hs[rg + 64][k];
            float a3 = Hs[rg + 96][k];
            const float* wr = &Ws[k][cg << 3];
            float4 w0 = *(const float4*)(wr + 0);
            float4 w1 = *(const float4*)(wr + 4);
#pragma unroll
            for (int j = 0; j < 4; ++j) {
                float wv = ((const float*)&w0)[j];
                ga[0][j] = fmaf(a0, wv, ga[0][j]);
                ga[1][j] = fmaf(a1, wv, ga[1][j]);
                ga[2][j] = fmaf(a2, wv, ga[2][j]);
                ga[3][j] = fmaf(a3, wv, ga[3][j]);
            }
#pragma unroll
            for (int j = 0; j < 4; ++j) {
                float wv = ((const float*)&w1)[j];
                ga[0][j + 4] = fmaf(a0, wv, ga[0][j + 4]);
                ga[1][j + 4] = fmaf(a1, wv, ga[1][j + 4]);
                ga[2][j + 4] = fmaf(a2, wv, ga[2][j + 4]);
                ga[3][j + 4] = fmaf(a3, wv, ga[3][j + 4]);
            }
        }

#pragma unroll
        for (int i = 0; i < 4; ++i) {
            const int mm = m0 + rg + i * 32;
#pragma unroll
            for (int j = 0; j < 8; ++j) {
                float v = ga[i][j];
                __half hi = __float2half_rn(v);
                __half lo = __float2half_rn(v - __half2float(hi));
                const int col = (cg << 3) + j;
                gouthi[(size_t)col * NN + mm] = hi;
                goutlo[(size_t)col * NN + mm] = lo;
            }
        }
    }
}

// ----------------------------------------------------------------
extern "C" void kernel_launch(void* const* d_in, const int* in_sizes, int n_in,
                              void* d_out, int out_size)
{
    const float* X    = (const float*)d_in[0];
    const float* L    = (const float*)d_in[1];
    const float* Wih0 = (const float*)d_in[2];
    const float* Whh0 = (const float*)d_in[3];
    const float* Wih1 = (const float*)d_in[4];
    const float* Whh1 = (const float*)d_in[5];
    float* out = (float*)d_out;

    float *wiu, *h, *part;
    __half *Lhi, *Llo, *gAhi, *gAlo, *gBhi, *gBlo;
    cudaGetSymbolAddress((void**)&wiu,  d_wiu);
    cudaGetSymbolAddress((void**)&h,    d_h);
    cudaGetSymbolAddress((void**)&part, d_part);
    cudaGetSymbolAddress((void**)&Lhi,  d_Lhi);
    cudaGetSymbolAddress((void**)&Llo,  d_Llo);
    cudaGetSymbolAddress((void**)&gAhi, d_gAhi);
    cudaGetSymbolAddress((void**)&gAlo, d_gAlo);
    cudaGetSymbolAddress((void**)&gBhi, d_gBhi);
    cudaGetSymbolAddress((void**)&gBlo, d_gBlo);

    const int DYN_SMEM = NSTAGE * STAGE_BYTES;   // 98304 -> 2 CTAs/SM
    cudaFuncSetAttribute(bigmma_k, cudaFuncAttributeMaxDynamicSharedMemorySize, DYN_SMEM);

    lsplit_k<<<(NN * NN) / (256 * 4), 256>>>(L, Lhi, Llo);

    for (int layer = 0; layer < 2; ++layer) {
        const float* Wih = layer ? Wih1 : Wih0;
        const float* Whh = layer ? Whh1 : Whh0;
        const float* Ain = layer ? h : X;

        small_gemm_k<<<64, 256>>>(Ain, Wih, wiu);
        init_k<<<128, 256>>>(wiu, Whh, gAhi, gAlo);

        for (int it = 0; it < 9; ++it) {
            const int last = (it == 8);
            const __half* gih = (it & 1) ? gBhi : gAhi;
            const __half* gil = (it & 1) ? gBlo : gAlo;
            __half* goh = (it & 1) ? gAhi : gBhi;
            __half* gol = (it & 1) ? gAlo : gBlo;
            bigmma_k<<<32 * KSPLIT, 256, DYN_SMEM>>>(
                Lhi, Llo, gih, gil, part, wiu, Whh, h, goh, gol,
                last ? out : nullptr, layer * 64, last);
        }
    }
}

// round 9
// speedup vs baseline: 1.7649x; 1.7649x over previous
#include <cuda_runtime.h>
#include <cuda_fp16.h>
#include <math.h>
#include <stdint.h>

#define NN 4096
#define HH 64
#define KSPLIT 8
#define LSCALE 256.0f
#define LDESCALE (1.0f / 256.0f)

// ---------------------------------------------------------------- scratch
__device__ float d_wiu[NN * HH];
__device__ float d_h[NN * HH];
__device__ float d_part[KSPLIT * NN * HH];
__device__ __half d_Lhi[(size_t)NN * NN];     // 256*L hi
__device__ __half d_Llo[(size_t)NN * NN];     // 256*L lo
__device__ __half d_gThi[HH * NN];            // g^T [64][4096]
__device__ __half d_gTlo[HH * NN];

// ---------------------------------------------------------------- PTX utils
__device__ __forceinline__ uint32_t smem_u32(const void* p) {
    uint32_t a;
    asm("{ .reg .u64 t; cvta.to.shared.u64 t, %1; cvt.u32.u64 %0, t; }"
        : "=r"(a) : "l"(p));
    return a;
}
#define SWZ128(o) ((o) ^ (((o) >> 3) & 0x70))

__device__ __forceinline__ void cp16(uint32_t s, const void* g) {
    asm volatile("cp.async.cg.shared.global [%0], [%1], 16;" :: "r"(s), "l"(g));
}
#define CP_COMMIT() asm volatile("cp.async.commit_group;" ::: "memory")
#define CP_WAIT1()  asm volatile("cp.async.wait_group 1;" ::: "memory")

// 256-bit STG with L2 evict_last priority (the only width ptxas accepts)
__device__ __forceinline__ void st_v8_evict_last(void* g, const uint32_t* r) {
    asm volatile(
        "st.global.L2::evict_last.v8.b32 [%0], {%1, %2, %3, %4, %5, %6, %7, %8};"
        :: "l"(g), "r"(r[0]), "r"(r[1]), "r"(r[2]), "r"(r[3]),
           "r"(r[4]), "r"(r[5]), "r"(r[6]), "r"(r[7]) : "memory");
}

__device__ __forceinline__ void ldsm_x4(uint32_t* r, uint32_t addr) {
    asm volatile("ldmatrix.sync.aligned.m8n8.x4.shared.b16 {%0,%1,%2,%3}, [%4];"
        : "=r"(r[0]), "=r"(r[1]), "=r"(r[2]), "=r"(r[3]) : "r"(addr));
}

__device__ __forceinline__ void mma16816(float* c, const uint32_t* a,
                                         uint32_t b0, uint32_t b1) {
    asm volatile(
        "mma.sync.aligned.m16n8k16.row.col.f32.f16.f16.f32 "
        "{%0,%1,%2,%3}, {%4,%5,%6,%7}, {%8,%9}, {%0,%1,%2,%3};"
        : "+f"(c[0]), "+f"(c[1]), "+f"(c[2]), "+f"(c[3])
        : "r"(a[0]), "r"(a[1]), "r"(a[2]), "r"(a[3]), "r"(b0), "r"(b1));
}

// ---------------------------------------------------------------- L split (once)
// Each thread handles 16 floats; hi/lo stores are 256-bit with L2::evict_last
// so Lhi/Llo stay L2-resident across all 18 big-GEMM steps.
__global__ __launch_bounds__(256, 4) void lsplit_k(
    const float* __restrict__ L,
    __half* __restrict__ Lhi, __half* __restrict__ Llo)
{
    size_t i = ((size_t)blockIdx.x * 256 + threadIdx.x) * 16;
    uint32_t hi[8], lo[8];
#pragma unroll
    for (int q = 0; q < 4; ++q) {
        float4 v = *(const float4*)(L + i + q * 4);
        float s0 = v.x * LSCALE, s1 = v.y * LSCALE;
        float s2 = v.z * LSCALE, s3 = v.w * LSCALE;
        __half h0 = __float2half_rn(s0), h1 = __float2half_rn(s1);
        __half h2 = __float2half_rn(s2), h3 = __float2half_rn(s3);
        __half l0 = __float2half_rn(s0 - __half2float(h0));
        __half l1 = __float2half_rn(s1 - __half2float(h1));
        __half l2 = __float2half_rn(s2 - __half2float(h2));
        __half l3 = __float2half_rn(s3 - __half2float(h3));
        __half2 hp0 = __halves2half2(h0, h1), hp1 = __halves2half2(h2, h3);
        __half2 lp0 = __halves2half2(l0, l1), lp1 = __halves2half2(l2, l3);
        hi[q * 2 + 0] = *(uint32_t*)&hp0; hi[q * 2 + 1] = *(uint32_t*)&hp1;
        lo[q * 2 + 0] = *(uint32_t*)&lp0; lo[q * 2 + 1] = *(uint32_t*)&lp1;
    }
    st_v8_evict_last(Lhi + i, hi);
    st_v8_evict_last(Llo + i, lo);
}

// ---------------------------------------------------------------- wiu small GEMM
__global__ __launch_bounds__(256, 1) void small_gemm_k(
    const float* __restrict__ A, const float* __restrict__ W,
    float* __restrict__ out)
{
    __shared__ float As[64][65];
    __shared__ float Ws[64][68];
    const int tid = threadIdx.x;
    const int base = blockIdx.x * (64 * 64);
    for (int i = tid; i < 4096; i += 256) {
        Ws[i & 63][i >> 6] = W[i];
        As[i >> 6][i & 63] = A[base + i];
    }
    __syncthreads();
    const int r = tid & 63, cg = tid >> 6;
    float acc[16];
#pragma unroll
    for (int j = 0; j < 16; ++j) acc[j] = 0.f;
#pragma unroll 8
    for (int k = 0; k < 64; ++k) {
        float a = As[r][k];
        const float* wr = &Ws[k][cg << 4];
        float4 b0 = *(const float4*)(wr + 0);
        float4 b1 = *(const float4*)(wr + 4);
        float4 b2 = *(const float4*)(wr + 8);
        float4 b3 = *(const float4*)(wr + 12);
        acc[0]  = fmaf(a, b0.x, acc[0]);  acc[1]  = fmaf(a, b0.y, acc[1]);
        acc[2]  = fmaf(a, b0.z, acc[2]);  acc[3]  = fmaf(a, b0.w, acc[3]);
        acc[4]  = fmaf(a, b1.x, acc[4]);  acc[5]  = fmaf(a, b1.y, acc[5]);
        acc[6]  = fmaf(a, b1.z, acc[6]);  acc[7]  = fmaf(a, b1.w, acc[7]);
        acc[8]  = fmaf(a, b2.x, acc[8]);  acc[9]  = fmaf(a, b2.y, acc[9]);
        acc[10] = fmaf(a, b2.z, acc[10]); acc[11] = fmaf(a, b2.w, acc[11]);
        acc[12] = fmaf(a, b3.x, acc[12]); acc[13] = fmaf(a, b3.y, acc[13]);
        acc[14] = fmaf(a, b3.z, acc[14]); acc[15] = fmaf(a, b3.w, acc[15]);
    }
    float* op = out + base + r * 64 + (cg << 4);
    *(float4*)(op + 0)  = make_float4(acc[0],  acc[1],  acc[2],  acc[3]);
    *(float4*)(op + 4)  = make_float4(acc[4],  acc[5],  acc[6],  acc[7]);
    *(float4*)(op + 8)  = make_float4(acc[8],  acc[9],  acc[10], acc[11]);
    *(float4*)(op + 12) = make_float4(acc[12], acc[13], acc[14], acc[15]);
}

// ---------------------------------------------------------------- reduce + tanh + g-split
__global__ __launch_bounds__(256, 2) void reduce_k(
    const float* __restrict__ wiu, const float* __restrict__ part, int nparts,
    const float* __restrict__ W, float* __restrict__ h,
    __half* __restrict__ gThi, __half* __restrict__ gTlo,
    float* __restrict__ outf, int col_off)
{
    __shared__ float Hs[32][65];
    __shared__ float Ws[64][68];
    const int tid = threadIdx.x;
    const int m0 = blockIdx.x * 32;

    if (!outf) {
        for (int i = tid; i < 4096; i += 256)
            Ws[i & 63][i >> 6] = W[i];
    }

    const int row = tid >> 3;
    const int c8 = (tid & 7) << 3;
    const int m = m0 + row;
    float z[8];
    {
        float s[8];
#pragma unroll
        for (int j = 0; j < 8; ++j) s[j] = 0.f;
        for (int p = 0; p < nparts; ++p) {
            const float* pp = part + (size_t)p * (NN * 64) + m * 64 + c8;
            float4 c = *(const float4*)(pp), d = *(const float4*)(pp + 4);
            s[0]+=c.x; s[1]+=c.y; s[2]+=c.z; s[3]+=c.w;
            s[4]+=d.x; s[5]+=d.y; s[6]+=d.z; s[7]+=d.w;
        }
        const float* wp = wiu + m * 64 + c8;
        float4 a = *(const float4*)(wp), b = *(const float4*)(wp + 4);
        z[0] = a.x + s[0]*LDESCALE; z[1] = a.y + s[1]*LDESCALE;
        z[2] = a.z + s[2]*LDESCALE; z[3] = a.w + s[3]*LDESCALE;
        z[4] = b.x + s[4]*LDESCALE; z[5] = b.y + s[5]*LDESCALE;
        z[6] = b.z + s[6]*LDESCALE; z[7] = b.w + s[7]*LDESCALE;
    }
#pragma unroll
    for (int j = 0; j < 8; ++j) z[j] = tanhf(z[j]);

    if (outf) {
        *(float4*)(h + m * 64 + c8)     = make_float4(z[0], z[1], z[2], z[3]);
        *(float4*)(h + m * 64 + c8 + 4) = make_float4(z[4], z[5], z[6], z[7]);
        float* op = outf + m * 128 + col_off + c8;
        *(float4*)(op)     = make_float4(z[0], z[1], z[2], z[3]);
        *(float4*)(op + 4) = make_float4(z[4], z[5], z[6], z[7]);
        return;
    }

#pragma unroll
    for (int j = 0; j < 8; ++j) Hs[row][c8 + j] = z[j];
    __syncthreads();

    const int r2 = tid & 31;
    const int cg2 = tid >> 5;
    float ga[8];
#pragma unroll
    for (int j = 0; j < 8; ++j) ga[j] = 0.f;
#pragma unroll 8
    for (int k = 0; k < 64; ++k) {
        float a = Hs[r2][k];
        const float* wr = &Ws[k][cg2 << 3];
        float4 w0 = *(const float4*)(wr + 0);
        float4 w1 = *(const float4*)(wr + 4);
        ga[0] = fmaf(a, w0.x, ga[0]); ga[1] = fmaf(a, w0.y, ga[1]);
        ga[2] = fmaf(a, w0.z, ga[2]); ga[3] = fmaf(a, w0.w, ga[3]);
        ga[4] = fmaf(a, w1.x, ga[4]); ga[5] = fmaf(a, w1.y, ga[5]);
        ga[6] = fmaf(a, w1.z, ga[6]); ga[7] = fmaf(a, w1.w, ga[7]);
    }
#pragma unroll
    for (int j = 0; j < 8; ++j) {
        float v = ga[j];
        __half hi = __float2half_rn(v);
        __half lo = __float2half_rn(v - __half2float(hi));
        int col = (cg2 << 3) + j;
        gThi[col * NN + m0 + r2] = hi;
        gTlo[col * NN + m0 + r2] = lo;
    }
}

// ---------------------------------------------------------------- big HMMA GEMM
// part[ks][4096][64] = K-split partial of (256*L) @ g, 3-term fp16 split
// grid 256 = 32 M-tiles x 8 K-splits; block 256 (8 warps: 2m x 4n, warp m64n16)
// 2 stages x 48KB -> 96KB/CTA -> 2 CTAs/SM
#define STAGE_BYTES 49152
#define NSTAGE 2
#define NCHUNK 8

__device__ __forceinline__ void load_stage(
    uint32_t st, int kbase, int m0, int tid,
    const __half* __restrict__ Lhi, const __half* __restrict__ Llo,
    const __half* __restrict__ gThi, const __half* __restrict__ gTlo)
{
#pragma unroll
    for (int r = 0; r < 4; ++r) {
        int o = tid + 256 * r;
        int row = o >> 3, seg = o & 7;
        uint32_t soff = SWZ128((uint32_t)(row * 128 + seg * 16));
        size_t goff = (size_t)(m0 + row) * NN + kbase + seg * 8;
        cp16(st + soff,         Lhi + goff);
        cp16(st + 16384 + soff, Llo + goff);
    }
#pragma unroll
    for (int r = 0; r < 2; ++r) {
        int o = tid + 256 * r;
        int row = o >> 3, seg = o & 7;
        uint32_t soff = SWZ128((uint32_t)(row * 128 + seg * 16));
        size_t goff = (size_t)row * NN + kbase + seg * 8;
        cp16(st + 32768 + soff, gThi + goff);
        cp16(st + 40960 + soff, gTlo + goff);
    }
    CP_COMMIT();
}

__global__ __launch_bounds__(256, 2) void bigmma_k(
    const __half* __restrict__ Lhi, const __half* __restrict__ Llo,
    const __half* __restrict__ gThi, const __half* __restrict__ gTlo,
    float* __restrict__ part)
{
    extern __shared__ __align__(1024) char smem[];
    const uint32_t sb = smem_u32(smem);
    const int tid = threadIdx.x;
    const int wid = tid >> 5, lane = tid & 31;
    const int mtile = blockIdx.x >> 3, ks = blockIdx.x & 7;
    const int m0 = mtile * 128;
    const int kbase0 = ks * 512;

    const int wm = wid >> 2;           // 0/1: m-range wm*64
    const int wn = wid & 3;            // n-range wn*16

    const int lrow8 = (lane & 7) + ((lane >> 3) & 1) * 8;
    const int lk16  = (lane >> 4) * 16;

    uint32_t arow[4];
#pragma unroll
    for (int t = 0; t < 4; ++t)
        arow[t] = (uint32_t)(wm * 64 + t * 16 + lrow8) * 128;
    const uint32_t brow = (uint32_t)(wn * 16 + lrow8) * 128;

    float acc[4][2][4];
#pragma unroll
    for (int t = 0; t < 4; ++t)
#pragma unroll
        for (int g = 0; g < 2; ++g)
#pragma unroll
            for (int j = 0; j < 4; ++j) acc[t][g][j] = 0.f;

#pragma unroll
    for (int c = 0; c < NSTAGE; ++c)
        load_stage(sb + c * STAGE_BYTES, kbase0 + c * 64, m0, tid,
                   Lhi, Llo, gThi, gTlo);

#pragma unroll 1
    for (int c = 0; c < NCHUNK; ++c) {
        CP_WAIT1();
        __syncthreads();

        const uint32_t st = sb + (c & 1) * STAGE_BYTES;
        const uint32_t stAhi = st, stAlo = st + 16384;
        const uint32_t stBhi = st + 32768, stBlo = st + 40960;

#pragma unroll
        for (int j = 0; j < 4; ++j) {
            const uint32_t kb = (uint32_t)(j * 32) + lk16;

            uint32_t bh[4], bl[4];
            ldsm_x4(bh, stBhi + SWZ128(brow + kb));
            ldsm_x4(bl, stBlo + SWZ128(brow + kb));

            uint32_t ah[4][4], al[4][4];
#pragma unroll
            for (int t = 0; t < 4; ++t) {
                ldsm_x4(ah[t], stAhi + SWZ128(arow[t] + kb));
                ldsm_x4(al[t], stAlo + SWZ128(arow[t] + kb));
            }

#pragma unroll
            for (int t = 0; t < 4; ++t) {
                mma16816(acc[t][0], ah[t], bh[0], bh[2]);
                mma16816(acc[t][1], ah[t], bh[1], bh[3]);
                mma16816(acc[t][0], al[t], bh[0], bh[2]);
                mma16816(acc[t][1], al[t], bh[1], bh[3]);
                mma16816(acc[t][0], ah[t], bl[0], bl[2]);
                mma16816(acc[t][1], ah[t], bl[1], bl[3]);
            }
        }
        __syncthreads();

        if (c + NSTAGE < NCHUNK)
            load_stage(st, kbase0 + (c + NSTAGE) * 64, m0, tid,
                       Lhi, Llo, gThi, gTlo);
        else
            CP_COMMIT();   // keep wait_group accounting valid
    }

    // epilogue: write partial tile
    const int l4 = lane >> 2;
    const int l2 = (lane & 3) * 2;
    float* pbase = part + (size_t)ks * (NN * 64);
#pragma unroll
    for (int t = 0; t < 4; ++t) {
        int mrow = m0 + wm * 64 + t * 16 + l4;
        float* p0 = pbase + (size_t)mrow * 64 + wn * 16;
        float* p1 = p0 + 8 * 64;
        *(float2*)(p0 + l2)     = make_float2(acc[t][0][0], acc[t][0][1]);
        *(float2*)(p0 + 8 + l2) = make_float2(acc[t][1][0], acc[t][1][1]);
        *(float2*)(p1 + l2)     = make_float2(acc[t][0][2], acc[t][0][3]);
        *(float2*)(p1 + 8 + l2) = make_float2(acc[t][1][2], acc[t][1][3]);
    }
}

// ----------------------------------------------------------------
extern "C" void kernel_launch(void* const* d_in, const int* in_sizes, int n_in,
                              void* d_out, int out_size)
{
    const float* X    = (const float*)d_in[0];
    const float* L    = (const float*)d_in[1];
    const float* Wih0 = (const float*)d_in[2];
    const float* Whh0 = (const float*)d_in[3];
    const float* Wih1 = (const float*)d_in[4];
    const float* Whh1 = (const float*)d_in[5];
    float* out = (float*)d_out;

    float *wiu, *h, *part;
    __half *Lhi, *Llo, *gThi, *gTlo;
    cudaGetSymbolAddress((void**)&wiu,  d_wiu);
    cudaGetSymbolAddress((void**)&h,    d_h);
    cudaGetSymbolAddress((void**)&part, d_part);
    cudaGetSymbolAddress((void**)&Lhi,  d_Lhi);
    cudaGetSymbolAddress((void**)&Llo,  d_Llo);
    cudaGetSymbolAddress((void**)&gThi, d_gThi);
    cudaGetSymbolAddress((void**)&gTlo, d_gTlo);

    const int DYN_SMEM = NSTAGE * STAGE_BYTES;   // 98304 -> 2 CTAs/SM
    cudaFuncSetAttribute(bigmma_k, cudaFuncAttributeMaxDynamicSharedMemorySize, DYN_SMEM);

    // one-time-per-launch: split 256*L into fp16 hi/lo (stores are L2-sticky)
    lsplit_k<<<(NN * NN) / (256 * 16), 256>>>(L, Lhi, Llo);

    for (int layer = 0; layer < 2; ++layer) {
        const float* Wih = layer ? Wih1 : Wih0;
        const float* Whh = layer ? Whh1 : Whh0;
        const float* Ain = layer ? h : X;

        small_gemm_k<<<64, 256>>>(Ain, Wih, wiu);
        // step 1: h = tanh(wiu), produce gT hi/lo
        reduce_k<<<128, 256>>>(wiu, part, 0, Whh, h, gThi, gTlo, nullptr, 0);

        // steps 2..10
        for (int it = 0; it < 9; ++it) {
            const int last = (it == 8);
            bigmma_k<<<256, 256, DYN_SMEM>>>(Lhi, Llo, gThi, gTlo, part);
            reduce_k<<<128, 256>>>(wiu, part, KSPLIT, Whh, h, gThi, gTlo,
                                   last ? out : nullptr, layer * 64);
        }
    }
}

// round 10
// speedup vs baseline: 1.8738x; 1.0617x over previous
#include <cuda_runtime.h>
#include <cuda_fp16.h>
#include <math.h>
#include <stdint.h>

#define NN 4096
#define HH 64
#define KSPLIT 7
#define NMTILE 64
#define LSCALE 256.0f
#define LDESCALE (1.0f / 256.0f)

// ---------------------------------------------------------------- scratch
__device__ float d_wiu[NN * HH];
__device__ float d_h[NN * HH];
__device__ float d_part[KSPLIT * NN * HH];
__device__ __half d_Lhi[(size_t)NN * NN];     // 256*L hi
__device__ __half d_Llo[(size_t)NN * NN];     // 256*L lo
__device__ __half d_gThi[HH * NN];            // g^T [64][4096]
__device__ __half d_gTlo[HH * NN];

// ---------------------------------------------------------------- PTX utils
__device__ __forceinline__ uint32_t smem_u32(const void* p) {
    uint32_t a;
    asm("{ .reg .u64 t; cvta.to.shared.u64 t, %1; cvt.u32.u64 %0, t; }"
        : "=r"(a) : "l"(p));
    return a;
}
#define SWZ128(o) ((o) ^ (((o) >> 3) & 0x70))

__device__ __forceinline__ void cp16(uint32_t s, const void* g) {
    asm volatile("cp.async.cg.shared.global [%0], [%1], 16;" :: "r"(s), "l"(g));
}
#define CP_COMMIT() asm volatile("cp.async.commit_group;" ::: "memory")
#define CP_WAIT1()  asm volatile("cp.async.wait_group 1;" ::: "memory")

__device__ __forceinline__ void st_v8_evict_last(void* g, const uint32_t* r) {
    asm volatile(
        "st.global.L2::evict_last.v8.b32 [%0], {%1, %2, %3, %4, %5, %6, %7, %8};"
        :: "l"(g), "r"(r[0]), "r"(r[1]), "r"(r[2]), "r"(r[3]),
           "r"(r[4]), "r"(r[5]), "r"(r[6]), "r"(r[7]) : "memory");
}

__device__ __forceinline__ void ldsm_x4(uint32_t* r, uint32_t addr) {
    asm volatile("ldmatrix.sync.aligned.m8n8.x4.shared.b16 {%0,%1,%2,%3}, [%4];"
        : "=r"(r[0]), "=r"(r[1]), "=r"(r[2]), "=r"(r[3]) : "r"(addr));
}

__device__ __forceinline__ void mma16816(float* c, const uint32_t* a,
                                         uint32_t b0, uint32_t b1) {
    asm volatile(
        "mma.sync.aligned.m16n8k16.row.col.f32.f16.f16.f32 "
        "{%0,%1,%2,%3}, {%4,%5,%6,%7}, {%8,%9}, {%0,%1,%2,%3};"
        : "+f"(c[0]), "+f"(c[1]), "+f"(c[2]), "+f"(c[3])
        : "r"(a[0]), "r"(a[1]), "r"(a[2]), "r"(a[3]), "r"(b0), "r"(b1));
}

// ---------------------------------------------------------------- L split (once)
__global__ __launch_bounds__(256, 4) void lsplit_k(
    const float* __restrict__ L,
    __half* __restrict__ Lhi, __half* __restrict__ Llo)
{
    size_t i = ((size_t)blockIdx.x * 256 + threadIdx.x) * 16;
    uint32_t hi[8], lo[8];
#pragma unroll
    for (int q = 0; q < 4; ++q) {
        float4 v = *(const float4*)(L + i + q * 4);
        float s0 = v.x * LSCALE, s1 = v.y * LSCALE;
        float s2 = v.z * LSCALE, s3 = v.w * LSCALE;
        __half h0 = __float2half_rn(s0), h1 = __float2half_rn(s1);
        __half h2 = __float2half_rn(s2), h3 = __float2half_rn(s3);
        __half l0 = __float2half_rn(s0 - __half2float(h0));
        __half l1 = __float2half_rn(s1 - __half2float(h1));
        __half l2 = __float2half_rn(s2 - __half2float(h2));
        __half l3 = __float2half_rn(s3 - __half2float(h3));
        __half2 hp0 = __halves2half2(h0, h1), hp1 = __halves2half2(h2, h3);
        __half2 lp0 = __halves2half2(l0, l1), lp1 = __halves2half2(l2, l3);
        hi[q * 2 + 0] = *(uint32_t*)&hp0; hi[q * 2 + 1] = *(uint32_t*)&hp1;
        lo[q * 2 + 0] = *(uint32_t*)&lp0; lo[q * 2 + 1] = *(uint32_t*)&lp1;
    }
    st_v8_evict_last(Lhi + i, hi);
    st_v8_evict_last(Llo + i, lo);
}

// ---------------------------------------------------------------- wiu small GEMM
__global__ __launch_bounds__(256, 1) void small_gemm_k(
    const float* __restrict__ A, const float* __restrict__ W,
    float* __restrict__ out)
{
    __shared__ float As[64][65];
    __shared__ float Ws[64][68];
    const int tid = threadIdx.x;
    const int base = blockIdx.x * (64 * 64);
    for (int i = tid; i < 4096; i += 256) {
        Ws[i & 63][i >> 6] = W[i];
        As[i >> 6][i & 63] = A[base + i];
    }
    __syncthreads();
    const int r = tid & 63, cg = tid >> 6;
    float acc[16];
#pragma unroll
    for (int j = 0; j < 16; ++j) acc[j] = 0.f;
#pragma unroll 8
    for (int k = 0; k < 64; ++k) {
        float a = As[r][k];
        const float* wr = &Ws[k][cg << 4];
        float4 b0 = *(const float4*)(wr + 0);
        float4 b1 = *(const float4*)(wr + 4);
        float4 b2 = *(const float4*)(wr + 8);
        float4 b3 = *(const float4*)(wr + 12);
        acc[0]  = fmaf(a, b0.x, acc[0]);  acc[1]  = fmaf(a, b0.y, acc[1]);
        acc[2]  = fmaf(a, b0.z, acc[2]);  acc[3]  = fmaf(a, b0.w, acc[3]);
        acc[4]  = fmaf(a, b1.x, acc[4]);  acc[5]  = fmaf(a, b1.y, acc[5]);
        acc[6]  = fmaf(a, b1.z, acc[6]);  acc[7]  = fmaf(a, b1.w, acc[7]);
        acc[8]  = fmaf(a, b2.x, acc[8]);  acc[9]  = fmaf(a, b2.y, acc[9]);
        acc[10] = fmaf(a, b2.z, acc[10]); acc[11] = fmaf(a, b2.w, acc[11]);
        acc[12] = fmaf(a, b3.x, acc[12]); acc[13] = fmaf(a, b3.y, acc[13]);
        acc[14] = fmaf(a, b3.z, acc[14]); acc[15] = fmaf(a, b3.w, acc[15]);
    }
    float* op = out + base + r * 64 + (cg << 4);
    *(float4*)(op + 0)  = make_float4(acc[0],  acc[1],  acc[2],  acc[3]);
    *(float4*)(op + 4)  = make_float4(acc[4],  acc[5],  acc[6],  acc[7]);
    *(float4*)(op + 8)  = make_float4(acc[8],  acc[9],  acc[10], acc[11]);
    *(float4*)(op + 12) = make_float4(acc[12], acc[13], acc[14], acc[15]);
}

// ---------------------------------------------------------------- reduce + tanh + g-split
__global__ __launch_bounds__(256, 2) void reduce_k(
    const float* __restrict__ wiu, const float* __restrict__ part, int nparts,
    const float* __restrict__ W, float* __restrict__ h,
    __half* __restrict__ gThi, __half* __restrict__ gTlo,
    float* __restrict__ outf, int col_off)
{
    __shared__ float Hs[32][65];
    __shared__ float Ws[64][68];
    const int tid = threadIdx.x;
    const int m0 = blockIdx.x * 32;

    if (!outf) {
        for (int i = tid; i < 4096; i += 256)
            Ws[i & 63][i >> 6] = W[i];
    }

    const int row = tid >> 3;
    const int c8 = (tid & 7) << 3;
    const int m = m0 + row;
    float z[8];
    {
        float s[8];
#pragma unroll
        for (int j = 0; j < 8; ++j) s[j] = 0.f;
        for (int p = 0; p < nparts; ++p) {
            const float* pp = part + (size_t)p * (NN * 64) + m * 64 + c8;
            float4 c = *(const float4*)(pp), d = *(const float4*)(pp + 4);
            s[0]+=c.x; s[1]+=c.y; s[2]+=c.z; s[3]+=c.w;
            s[4]+=d.x; s[5]+=d.y; s[6]+=d.z; s[7]+=d.w;
        }
        const float* wp = wiu + m * 64 + c8;
        float4 a = *(const float4*)(wp), b = *(const float4*)(wp + 4);
        z[0] = a.x + s[0]*LDESCALE; z[1] = a.y + s[1]*LDESCALE;
        z[2] = a.z + s[2]*LDESCALE; z[3] = a.w + s[3]*LDESCALE;
        z[4] = b.x + s[4]*LDESCALE; z[5] = b.y + s[5]*LDESCALE;
        z[6] = b.z + s[6]*LDESCALE; z[7] = b.w + s[7]*LDESCALE;
    }
#pragma unroll
    for (int j = 0; j < 8; ++j) z[j] = tanhf(z[j]);

    if (outf) {
        *(float4*)(h + m * 64 + c8)     = make_float4(z[0], z[1], z[2], z[3]);
        *(float4*)(h + m * 64 + c8 + 4) = make_float4(z[4], z[5], z[6], z[7]);
        float* op = outf + m * 128 + col_off + c8;
        *(float4*)(op)     = make_float4(z[0], z[1], z[2], z[3]);
        *(float4*)(op + 4) = make_float4(z[4], z[5], z[6], z[7]);
        return;
    }

#pragma unroll
    for (int j = 0; j < 8; ++j) Hs[row][c8 + j] = z[j];
    __syncthreads();

    const int r2 = tid & 31;
    const int cg2 = tid >> 5;
    float ga[8];
#pragma unroll
    for (int j = 0; j < 8; ++j) ga[j] = 0.f;
#pragma unroll 8
    for (int k = 0; k < 64; ++k) {
        float a = Hs[r2][k];
        const float* wr = &Ws[k][cg2 << 3];
        float4 w0 = *(const float4*)(wr + 0);
        float4 w1 = *(const float4*)(wr + 4);
        ga[0] = fmaf(a, w0.x, ga[0]); ga[1] = fmaf(a, w0.y, ga[1]);
        ga[2] = fmaf(a, w0.z, ga[2]); ga[3] = fmaf(a, w0.w, ga[3]);
        ga[4] = fmaf(a, w1.x, ga[4]); ga[5] = fmaf(a, w1.y, ga[5]);
        ga[6] = fmaf(a, w1.z, ga[6]); ga[7] = fmaf(a, w1.w, ga[7]);
    }
#pragma unroll
    for (int j = 0; j < 8; ++j) {
        float v = ga[j];
        __half hi = __float2half_rn(v);
        __half lo = __float2half_rn(v - __half2float(hi));
        int col = (cg2 << 3) + j;
        gThi[col * NN + m0 + r2] = hi;
        gTlo[col * NN + m0 + r2] = lo;
    }
}

// ---------------------------------------------------------------- big HMMA GEMM
// part[ks][4096][64] = K-split partial of (256*L) @ g, 3-term fp16 split
// grid 448 = 64 M-tiles(64 rows) x 7 K-splits; block 256 (8 warps: 2m x 4n, warp m32n16)
// 2 stages x 32KB -> 64KB/CTA -> 3 CTAs/SM
#define STAGE_BYTES 32768
#define NSTAGE 2

__device__ __forceinline__ void load_stage(
    uint32_t st, int kbase, int m0, int tid,
    const __half* __restrict__ Lhi, const __half* __restrict__ Llo,
    const __half* __restrict__ gThi, const __half* __restrict__ gTlo)
{
    // A: 64 rows x 128B, hi @0, lo @8192
#pragma unroll
    for (int r = 0; r < 2; ++r) {
        int o = tid + 256 * r;
        int row = o >> 3, seg = o & 7;
        uint32_t soff = SWZ128((uint32_t)(row * 128 + seg * 16));
        size_t goff = (size_t)(m0 + row) * NN + kbase + seg * 8;
        cp16(st + soff,        Lhi + goff);
        cp16(st + 8192 + soff, Llo + goff);
    }
    // B: 64 rows (g^T cols) x 128B, hi @16384, lo @24576
#pragma unroll
    for (int r = 0; r < 2; ++r) {
        int o = tid + 256 * r;
        int row = o >> 3, seg = o & 7;
        uint32_t soff = SWZ128((uint32_t)(row * 128 + seg * 16));
        size_t goff = (size_t)row * NN + kbase + seg * 8;
        cp16(st + 16384 + soff, gThi + goff);
        cp16(st + 24576 + soff, gTlo + goff);
    }
    CP_COMMIT();
}

__global__ __launch_bounds__(256, 3) void bigmma_k(
    const __half* __restrict__ Lhi, const __half* __restrict__ Llo,
    const __half* __restrict__ gThi, const __half* __restrict__ gTlo,
    float* __restrict__ part)
{
    extern __shared__ __align__(1024) char smem[];
    const uint32_t sb = smem_u32(smem);
    const int tid = threadIdx.x;
    const int wid = tid >> 5, lane = tid & 31;
    const int mtile = blockIdx.x / KSPLIT, ks = blockIdx.x % KSPLIT;
    const int m0 = mtile * 64;
    const int kbase0 = ks * 9 * 64;
    const int nchunk = (ks == KSPLIT - 1) ? 10 : 9;   // 6*9 + 10 = 64

    const int wm = wid >> 2;           // 0/1: m-range wm*32
    const int wn = wid & 3;            // n-range wn*16

    const int lrow8 = (lane & 7) + ((lane >> 3) & 1) * 8;
    const int lk16  = (lane >> 4) * 16;

    uint32_t arow[2];
#pragma unroll
    for (int t = 0; t < 2; ++t)
        arow[t] = (uint32_t)(wm * 32 + t * 16 + lrow8) * 128;
    const uint32_t brow = (uint32_t)(wn * 16 + lrow8) * 128;

    float acc[2][2][4];
#pragma unroll
    for (int t = 0; t < 2; ++t)
#pragma unroll
        for (int g = 0; g < 2; ++g)
#pragma unroll
            for (int j = 0; j < 4; ++j) acc[t][g][j] = 0.f;

#pragma unroll
    for (int c = 0; c < NSTAGE; ++c)
        load_stage(sb + c * STAGE_BYTES, kbase0 + c * 64, m0, tid,
                   Lhi, Llo, gThi, gTlo);

#pragma unroll 1
    for (int c = 0; c < nchunk; ++c) {
        CP_WAIT1();
        __syncthreads();

        const uint32_t st = sb + (c & 1) * STAGE_BYTES;
        const uint32_t stAhi = st, stAlo = st + 8192;
        const uint32_t stBhi = st + 16384, stBlo = st + 24576;

#pragma unroll
        for (int j = 0; j < 4; ++j) {
            const uint32_t kb = (uint32_t)(j * 32) + lk16;

            uint32_t bh[4], bl[4];
            ldsm_x4(bh, stBhi + SWZ128(brow + kb));
            ldsm_x4(bl, stBlo + SWZ128(brow + kb));

            uint32_t ah[2][4], al[2][4];
#pragma unroll
            for (int t = 0; t < 2; ++t) {
                ldsm_x4(ah[t], stAhi + SWZ128(arow[t] + kb));
                ldsm_x4(al[t], stAlo + SWZ128(arow[t] + kb));
            }

#pragma unroll
            for (int t = 0; t < 2; ++t) {
                mma16816(acc[t][0], ah[t], bh[0], bh[2]);
                mma16816(acc[t][1], ah[t], bh[1], bh[3]);
                mma16816(acc[t][0], al[t], bh[0], bh[2]);
                mma16816(acc[t][1], al[t], bh[1], bh[3]);
                mma16816(acc[t][0], ah[t], bl[0], bl[2]);
                mma16816(acc[t][1], ah[t], bl[1], bl[3]);
            }
        }
        __syncthreads();

        if (c + NSTAGE < nchunk)
            load_stage(st, kbase0 + (c + NSTAGE) * 64, m0, tid,
                       Lhi, Llo, gThi, gTlo);
        else
            CP_COMMIT();   // keep wait_group accounting valid
    }

    // epilogue: write partial tile
    const int l4 = lane >> 2;
    const int l2 = (lane & 3) * 2;
    float* pbase = part + (size_t)ks * (NN * 64);
#pragma unroll
    for (int t = 0; t < 2; ++t) {
        int mrow = m0 + wm * 32 + t * 16 + l4;
        float* p0 = pbase + (size_t)mrow * 64 + wn * 16;
        float* p1 = p0 + 8 * 64;
        *(float2*)(p0 + l2)     = make_float2(acc[t][0][0], acc[t][0][1]);
        *(float2*)(p0 + 8 + l2) = make_float2(acc[t][1][0], acc[t][1][1]);
        *(float2*)(p1 + l2)     = make_float2(acc[t][0][2], acc[t][0][3]);
        *(float2*)(p1 + 8 + l2) = make_float2(acc[t][1][2], acc[t][1][3]);
    }
}

// ----------------------------------------------------------------
extern "C" void kernel_launch(void* const* d_in, const int* in_sizes, int n_in,
                              void* d_out, int out_size)
{
    const float* X    = (const float*)d_in[0];
    const float* L    = (const float*)d_in[1];
    const float* Wih0 = (const float*)d_in[2];
    const float* Whh0 = (const float*)d_in[3];
    const float* Wih1 = (const float*)d_in[4];
    const float* Whh1 = (const float*)d_in[5];
    float* out = (float*)d_out;

    float *wiu, *h, *part;
    __half *Lhi, *Llo, *gThi, *gTlo;
    cudaGetSymbolAddress((void**)&wiu,  d_wiu);
    cudaGetSymbolAddress((void**)&h,    d_h);
    cudaGetSymbolAddress((void**)&part, d_part);
    cudaGetSymbolAddress((void**)&Lhi,  d_Lhi);
    cudaGetSymbolAddress((void**)&Llo,  d_Llo);
    cudaGetSymbolAddress((void**)&gThi, d_gThi);
    cudaGetSymbolAddress((void**)&gTlo, d_gTlo);

    const int DYN_SMEM = NSTAGE * STAGE_BYTES;   // 65536 -> 3 CTAs/SM
    cudaFuncSetAttribute(bigmma_k, cudaFuncAttributeMaxDynamicSharedMemorySize, DYN_SMEM);

    // one-time-per-launch: split 256*L into fp16 hi/lo
    lsplit_k<<<(NN * NN) / (256 * 16), 256>>>(L, Lhi, Llo);

    for (int layer = 0; layer < 2; ++layer) {
        const float* Wih = layer ? Wih1 : Wih0;
        const float* Whh = layer ? Whh1 : Whh0;
        const float* Ain = layer ? h : X;

        small_gemm_k<<<64, 256>>>(Ain, Wih, wiu);
        // step 1: h = tanh(wiu), produce gT hi/lo
        reduce_k<<<128, 256>>>(wiu, part, 0, Whh, h, gThi, gTlo, nullptr, 0);

        // steps 2..10
        for (int it = 0; it < 9; ++it) {
            const int last = (it == 8);
            bigmma_k<<<64 * KSPLIT, 256, DYN_SMEM>>>(Lhi, Llo, gThi, gTlo, part);
            reduce_k<<<128, 256>>>(wiu, part, KSPLIT, Whh, h, gThi, gTlo,
                                   last ? out : nullptr, layer * 64);
        }
    }
}